// round 14
// baseline (speedup 1.0000x reference)
#include <cuda_runtime.h>
#include <cstdint>

#define B_  2
#define H_  12
#define S_  2048
#define D_  64
#define BH_ (B_ * H_)
#define SCALE_ 0.125f   // 1/sqrt(64)

#define QK_PAD 68       // stride ≡ 4 (mod 32) -> conflict-free fragment LDS
#define QK_SMEM_BYTES (2 * 128 * QK_PAD * 4)

#define AV_PAD 36       // stride ≡ 4 (mod 32), same property
// Pre-split planes: Phi/Plo [128][36], VThi/VTlo [64][36], all u32.
#define AV_SMEM_WORDS (2 * 128 * AV_PAD + 2 * 64 * AV_PAD)
#define AV_SMEM_BYTES (AV_SMEM_WORDS * 4)

// ---------------------------------------------------------------------------
// tf32 helpers
// ---------------------------------------------------------------------------
__device__ __forceinline__ uint32_t f2tf32(float x)
{
    uint32_t r;
    asm("cvt.rna.tf32.f32 %0, %1;" : "=r"(r) : "f"(x));
    return r;
}

__device__ __forceinline__ void split_tf32(float x, uint32_t& hi, uint32_t& lo)
{
    hi = f2tf32(x);
    lo = f2tf32(x - __uint_as_float(hi));
}

__device__ __forceinline__ void mma_tf32(float* c, const uint32_t* a, const uint32_t* b)
{
    asm("mma.sync.aligned.m16n8k8.row.col.f32.tf32.tf32.f32 "
        "{%0,%1,%2,%3}, {%4,%5,%6,%7}, {%8,%9}, {%0,%1,%2,%3};"
        : "+f"(c[0]), "+f"(c[1]), "+f"(c[2]), "+f"(c[3])
        : "r"(a[0]), "r"(a[1]), "r"(a[2]), "r"(a[3]), "r"(b[0]), "r"(b[1]));
}

// ---------------------------------------------------------------------------
// Kernel 1: QK^T via 3xTF32 tensor-core MMA + mask epilogue. (R11, verified)
// ---------------------------------------------------------------------------
__global__ __launch_bounds__(256)
void qk_tf32_kernel(const float* __restrict__ q, const float* __restrict__ k,
                    const int* __restrict__ mask, float* __restrict__ attn)
{
    extern __shared__ float smem[];
    float* sQ = smem;                 // [128][QK_PAD]
    float* sK = smem + 128 * QK_PAD;  // [128][QK_PAD]

    const int bh = blockIdx.z;
    const int b  = bh / H_;
    const int q0 = blockIdx.y * 128;
    const int k0 = blockIdx.x * 128;
    const int t    = threadIdx.x;
    const int lane = t & 31;
    const int wid  = t >> 5;
    const int wm   = wid >> 1;        // 0..3 -> q rows [wm*32, +32)
    const int wn   = wid & 1;         // 0..1 -> k cols [wn*64, +64)
    const int g    = lane >> 2;       // groupID 0..7
    const int tg   = lane & 3;        // thread-in-group 0..3

    const float* Qb = q + ((size_t)bh * S_ + q0) * D_;
    const float* Kb = k + ((size_t)bh * S_ + k0) * D_;

#pragma unroll
    for (int i = 0; i < 8; i++) {
        int vid = t + i * 256;
        int row = vid >> 4;           // 0..127
        int c4  = (vid & 15) * 4;     // 0..60
        *(float4*)&sQ[row * QK_PAD + c4] = *(const float4*)(Qb + (size_t)row * D_ + c4);
        *(float4*)&sK[row * QK_PAD + c4] = *(const float4*)(Kb + (size_t)row * D_ + c4);
    }
    __syncthreads();

    float acc[2][8][4];
#pragma unroll
    for (int mt = 0; mt < 2; mt++)
#pragma unroll
        for (int nt = 0; nt < 8; nt++)
#pragma unroll
            for (int r = 0; r < 4; r++) acc[mt][nt][r] = 0.0f;

#pragma unroll
    for (int ks = 0; ks < 8; ks++) {
        const int kb = ks * 8 + tg;

        uint32_t ahi[2][4], alo[2][4];
#pragma unroll
        for (int mt = 0; mt < 2; mt++) {
            int r = wm * 32 + mt * 16 + g;
            split_tf32(sQ[r * QK_PAD + kb],           ahi[mt][0], alo[mt][0]);
            split_tf32(sQ[(r + 8) * QK_PAD + kb],     ahi[mt][1], alo[mt][1]);
            split_tf32(sQ[r * QK_PAD + kb + 4],       ahi[mt][2], alo[mt][2]);
            split_tf32(sQ[(r + 8) * QK_PAD + kb + 4], ahi[mt][3], alo[mt][3]);
        }

        uint32_t bhi[8][2], blo[8][2];
#pragma unroll
        for (int nt = 0; nt < 8; nt++) {
            int cc = wn * 64 + nt * 8 + g;
            split_tf32(sK[cc * QK_PAD + kb],     bhi[nt][0], blo[nt][0]);
            split_tf32(sK[cc * QK_PAD + kb + 4], bhi[nt][1], blo[nt][1]);
        }

#pragma unroll
        for (int mt = 0; mt < 2; mt++)
#pragma unroll
            for (int nt = 0; nt < 8; nt++) {
                mma_tf32(acc[mt][nt], ahi[mt], bhi[nt]);
                mma_tf32(acc[mt][nt], ahi[mt], blo[nt]);
                mma_tf32(acc[mt][nt], alo[mt], bhi[nt]);
            }
    }

#pragma unroll
    for (int mt = 0; mt < 2; mt++)
#pragma unroll
        for (int nt = 0; nt < 8; nt++)
#pragma unroll
            for (int rr = 0; rr < 2; rr++) {
                int qq = q0 + wm * 32 + mt * 16 + g + 8 * rr;
                int kc = k0 + wn * 64 + nt * 8 + 2 * tg;
                int2 m2 = *(const int2*)(mask + ((size_t)b * S_ + qq) * S_ + kc);
                float2 r;
                r.x = (m2.x == 0) ? 1e-9f : acc[mt][nt][2 * rr + 0] * SCALE_;
                r.y = (m2.y == 0) ? 1e-9f : acc[mt][nt][2 * rr + 1] * SCALE_;
                *(float2*)(attn + ((size_t)bh * S_ + qq) * S_ + kc) = r;
            }
}

// ---------------------------------------------------------------------------
// Kernel 2: in-place row softmax over the attention region. (R2, verified)
// ---------------------------------------------------------------------------
__global__ __launch_bounds__(256)
void softmax_kernel(float* __restrict__ attn)
{
    __shared__ float smax[8];
    __shared__ float ssum[8];

    const size_t row = blockIdx.x;          // bh*S + q
    float* p = attn + row * S_;
    const int t    = threadIdx.x;
    const int wid  = t >> 5;
    const int lane = t & 31;

    float4 v0 = ((const float4*)p)[t];
    float4 v1 = ((const float4*)p)[t + 256];

    float m = fmaxf(fmaxf(fmaxf(v0.x, v0.y), fmaxf(v0.z, v0.w)),
                    fmaxf(fmaxf(v1.x, v1.y), fmaxf(v1.z, v1.w)));
#pragma unroll
    for (int o = 16; o > 0; o >>= 1)
        m = fmaxf(m, __shfl_xor_sync(0xffffffffu, m, o));
    if (lane == 0) smax[wid] = m;
    __syncthreads();
    float mr = smax[0];
#pragma unroll
    for (int i = 1; i < 8; i++) mr = fmaxf(mr, smax[i]);

    float e0x = __expf(v0.x - mr), e0y = __expf(v0.y - mr);
    float e0z = __expf(v0.z - mr), e0w = __expf(v0.w - mr);
    float e1x = __expf(v1.x - mr), e1y = __expf(v1.y - mr);
    float e1z = __expf(v1.z - mr), e1w = __expf(v1.w - mr);

    float s = ((e0x + e0y) + (e0z + e0w)) + ((e1x + e1y) + (e1z + e1w));
#pragma unroll
    for (int o = 16; o > 0; o >>= 1)
        s += __shfl_xor_sync(0xffffffffu, s, o);
    if (lane == 0) ssum[wid] = s;
    __syncthreads();
    float total = ssum[0];
#pragma unroll
    for (int i = 1; i < 8; i++) total += ssum[i];

    float inv = 1.0f / total;
    float4 r0 = make_float4(e0x * inv, e0y * inv, e0z * inv, e0w * inv);
    float4 r1 = make_float4(e1x * inv, e1y * inv, e1z * inv, e1w * inv);
    ((float4*)p)[t]       = r0;
    ((float4*)p)[t + 256] = r1;
}

// ---------------------------------------------------------------------------
// Kernel 3: output = P @ V via 3xTF32 MMA with PRE-SPLIT hi/lo smem planes.
// C-tile 128q x 64d, 256 threads (8 warps, 4m x 2n), warp tile 32x32.
// Split happens once per element at chunk load; mainloop is LDS + MMA only.
// ---------------------------------------------------------------------------
__global__ __launch_bounds__(256)
void av_tf32_kernel(const float* __restrict__ attn, const float* __restrict__ v,
                    float* __restrict__ out)
{
    extern __shared__ uint32_t dsm[];
    uint32_t* sPhi  = dsm;                        // [128][AV_PAD]
    uint32_t* sPlo  = sPhi  + 128 * AV_PAD;       // [128][AV_PAD]
    uint32_t* sVhi  = sPlo  + 128 * AV_PAD;       // [64][AV_PAD] (transposed V)
    uint32_t* sVlo  = sVhi  + 64 * AV_PAD;        // [64][AV_PAD]

    const int bh = blockIdx.y;
    const int q0 = blockIdx.x * 128;
    const int t    = threadIdx.x;
    const int lane = t & 31;
    const int wid  = t >> 5;
    const int wm   = wid >> 1;        // 0..3 -> q rows [wm*32, +32)
    const int wn   = wid & 1;         // 0..1 -> d cols [wn*32, +32)
    const int g    = lane >> 2;
    const int tg   = lane & 3;

    const float* Pb = attn + ((size_t)bh * S_ + q0) * S_;
    const float* Vb = v + (size_t)bh * S_ * D_;

    // V transpose-load mapping: lane = k-row (conflict-free STS), warp-constant d.
    const int vrow = t & 31;          // k-row within chunk
    const int vc4  = (t >> 5) * 4;    // d-offset 0..28 (with i*32: 0..60)

    float acc[2][4][4];
#pragma unroll
    for (int mt = 0; mt < 2; mt++)
#pragma unroll
        for (int nt = 0; nt < 4; nt++)
#pragma unroll
            for (int r = 0; r < 4; r++) acc[mt][nt][r] = 0.0f;

    for (int c0 = 0; c0 < S_; c0 += 32) {
        // P chunk 128x32: 1024 float4, 4/thread, coalesced; split at store.
#pragma unroll
        for (int i = 0; i < 4; i++) {
            int vid = t + i * 256;
            int row = vid >> 3;           // 0..127
            int c4  = (vid & 7) * 4;      // 0..28
            float4 a = *(const float4*)(Pb + (size_t)row * S_ + c0 + c4);
            uint32_t hi, lo;
            split_tf32(a.x, hi, lo); sPhi[row * AV_PAD + c4 + 0] = hi; sPlo[row * AV_PAD + c4 + 0] = lo;
            split_tf32(a.y, hi, lo); sPhi[row * AV_PAD + c4 + 1] = hi; sPlo[row * AV_PAD + c4 + 1] = lo;
            split_tf32(a.z, hi, lo); sPhi[row * AV_PAD + c4 + 2] = hi; sPlo[row * AV_PAD + c4 + 2] = lo;
            split_tf32(a.w, hi, lo); sPhi[row * AV_PAD + c4 + 3] = hi; sPlo[row * AV_PAD + c4 + 3] = lo;
        }
        // V chunk 32x64 -> transposed [d][k]; split at store.
#pragma unroll
        for (int i = 0; i < 2; i++) {
            int dd = vc4 + i * 32;
            float4 b = *(const float4*)(Vb + (size_t)(c0 + vrow) * D_ + dd);
            uint32_t hi, lo;
            split_tf32(b.x, hi, lo); sVhi[(dd + 0) * AV_PAD + vrow] = hi; sVlo[(dd + 0) * AV_PAD + vrow] = lo;
            split_tf32(b.y, hi, lo); sVhi[(dd + 1) * AV_PAD + vrow] = hi; sVlo[(dd + 1) * AV_PAD + vrow] = lo;
            split_tf32(b.z, hi, lo); sVhi[(dd + 2) * AV_PAD + vrow] = hi; sVlo[(dd + 2) * AV_PAD + vrow] = lo;
            split_tf32(b.w, hi, lo); sVhi[(dd + 3) * AV_PAD + vrow] = hi; sVlo[(dd + 3) * AV_PAD + vrow] = lo;
        }
        __syncthreads();

#pragma unroll
        for (int ks = 0; ks < 4; ks++) {
            const int kb = ks * 8 + tg;

            uint32_t ahi[2][4], alo[2][4];
#pragma unroll
            for (int mt = 0; mt < 2; mt++) {
                int r = wm * 32 + mt * 16 + g;
                ahi[mt][0] = sPhi[r * AV_PAD + kb];           alo[mt][0] = sPlo[r * AV_PAD + kb];
                ahi[mt][1] = sPhi[(r + 8) * AV_PAD + kb];     alo[mt][1] = sPlo[(r + 8) * AV_PAD + kb];
                ahi[mt][2] = sPhi[r * AV_PAD + kb + 4];       alo[mt][2] = sPlo[r * AV_PAD + kb + 4];
                ahi[mt][3] = sPhi[(r + 8) * AV_PAD + kb + 4]; alo[mt][3] = sPlo[(r + 8) * AV_PAD + kb + 4];
            }

            uint32_t bhi[4][2], blo[4][2];
#pragma unroll
            for (int nt = 0; nt < 4; nt++) {
                int cc = wn * 32 + nt * 8 + g;
                bhi[nt][0] = sVhi[cc * AV_PAD + kb];     blo[nt][0] = sVlo[cc * AV_PAD + kb];
                bhi[nt][1] = sVhi[cc * AV_PAD + kb + 4]; blo[nt][1] = sVlo[cc * AV_PAD + kb + 4];
            }

#pragma unroll
            for (int mt = 0; mt < 2; mt++)
#pragma unroll
                for (int nt = 0; nt < 4; nt++) {
                    mma_tf32(acc[mt][nt], ahi[mt], bhi[nt]);
                    mma_tf32(acc[mt][nt], ahi[mt], blo[nt]);
                    mma_tf32(acc[mt][nt], alo[mt], bhi[nt]);
                }
        }
        __syncthreads();
    }

    // Epilogue: same C fragment layout as qk.
#pragma unroll
    for (int mt = 0; mt < 2; mt++)
#pragma unroll
        for (int nt = 0; nt < 4; nt++)
#pragma unroll
            for (int rr = 0; rr < 2; rr++) {
                int qq = q0 + wm * 32 + mt * 16 + g + 8 * rr;
                int dc = wn * 32 + nt * 8 + 2 * tg;
                float2 r;
                r.x = acc[mt][nt][2 * rr + 0];
                r.y = acc[mt][nt][2 * rr + 1];
                *(float2*)(out + ((size_t)bh * S_ + qq) * D_ + dc) = r;
            }
}

// ---------------------------------------------------------------------------
// Launch: out buffer = [output (B,H,S,D) | attention (B,H,S,S)]
// ---------------------------------------------------------------------------
extern "C" void kernel_launch(void* const* d_in, const int* in_sizes, int n_in,
                              void* d_out, int out_size)
{
    const float* q    = (const float*)d_in[0];
    const float* k    = (const float*)d_in[1];
    const float* v    = (const float*)d_in[2];
    const int*   mask = (const int*)d_in[3];

    float* out  = (float*)d_out;
    float* attn = out + (size_t)BH_ * S_ * D_;

    cudaFuncSetAttribute(qk_tf32_kernel,
                         cudaFuncAttributeMaxDynamicSharedMemorySize,
                         QK_SMEM_BYTES);
    cudaFuncSetAttribute(av_tf32_kernel,
                         cudaFuncAttributeMaxDynamicSharedMemorySize,
                         AV_SMEM_BYTES);

    dim3 g1(S_ / 128, S_ / 128, BH_);
    qk_tf32_kernel<<<g1, 256, QK_SMEM_BYTES>>>(q, k, mask, attn);

    softmax_kernel<<<(unsigned)(BH_ * S_), 256>>>(attn);

    dim3 g3(S_ / 128, BH_);
    av_tf32_kernel<<<g3, 256, AV_SMEM_BYTES>>>(attn, v, out);
}

// round 17
// speedup vs baseline: 1.3722x; 1.3722x over previous
#include <cuda_runtime.h>
#include <cstdint>

#define B_  2
#define H_  12
#define S_  2048
#define D_  64
#define BH_ (B_ * H_)
#define SCALE_ 0.125f   // 1/sqrt(64)

#define QK_PAD 68       // stride ≡ 4 (mod 32) -> conflict-free fragment LDS
#define QK_SMEM_BYTES (2 * 128 * QK_PAD * 4)

#define AV_PAD 36       // stride ≡ 4 (mod 32), same property
#define AV_SMEM_WORDS (2 * 128 * AV_PAD + 2 * 64 * AV_PAD)
#define AV_SMEM_BYTES (AV_SMEM_WORDS * 4)

// Per-row sums of unnormalized exp(logit). 24*2048 floats. (R3-verified pattern)
__device__ float g_rowsum[BH_ * S_];

// ---------------------------------------------------------------------------
// tf32 helpers
// ---------------------------------------------------------------------------
__device__ __forceinline__ uint32_t f2tf32(float x)
{
    uint32_t r;
    asm("cvt.rna.tf32.f32 %0, %1;" : "=r"(r) : "f"(x));
    return r;
}

__device__ __forceinline__ void split_tf32(float x, uint32_t& hi, uint32_t& lo)
{
    hi = f2tf32(x);
    lo = f2tf32(x - __uint_as_float(hi));
}

__device__ __forceinline__ void mma_tf32(float* c, const uint32_t* a, const uint32_t* b)
{
    asm("mma.sync.aligned.m16n8k8.row.col.f32.tf32.tf32.f32 "
        "{%0,%1,%2,%3}, {%4,%5,%6,%7}, {%8,%9}, {%0,%1,%2,%3};"
        : "+f"(c[0]), "+f"(c[1]), "+f"(c[2]), "+f"(c[3])
        : "r"(a[0]), "r"(a[1]), "r"(a[2]), "r"(a[3]), "r"(b[0]), "r"(b[1]));
}

// ---------------------------------------------------------------------------
// Kernel 0: zero the rowsum accumulator.
// ---------------------------------------------------------------------------
__global__ void zero_rowsum_kernel()
{
    g_rowsum[blockIdx.x * 256 + threadIdx.x] = 0.0f;
}

// ---------------------------------------------------------------------------
// Kernel 1: QK^T via 3xTF32 MMA; epilogue: mask -> exp (no-max softmax,
// R3-verified), write unnormalized E, accumulate per-row sums via atomics.
// Mainloop identical to R11/R12 (measured).
// ---------------------------------------------------------------------------
__global__ __launch_bounds__(256)
void qk_tf32_kernel(const float* __restrict__ q, const float* __restrict__ k,
                    const int* __restrict__ mask, float* __restrict__ attn)
{
    extern __shared__ float smem[];
    float* sQ = smem;                 // [128][QK_PAD]
    float* sK = smem + 128 * QK_PAD;  // [128][QK_PAD]

    const int bh = blockIdx.z;
    const int b  = bh / H_;
    const int q0 = blockIdx.y * 128;
    const int k0 = blockIdx.x * 128;
    const int t    = threadIdx.x;
    const int lane = t & 31;
    const int wid  = t >> 5;
    const int wm   = wid >> 1;        // 0..3 -> q rows [wm*32, +32)
    const int wn   = wid & 1;         // 0..1 -> k cols [wn*64, +64)
    const int g    = lane >> 2;       // groupID 0..7
    const int tg   = lane & 3;        // thread-in-group 0..3

    const float* Qb = q + ((size_t)bh * S_ + q0) * D_;
    const float* Kb = k + ((size_t)bh * S_ + k0) * D_;

#pragma unroll
    for (int i = 0; i < 8; i++) {
        int vid = t + i * 256;
        int row = vid >> 4;           // 0..127
        int c4  = (vid & 15) * 4;     // 0..60
        *(float4*)&sQ[row * QK_PAD + c4] = *(const float4*)(Qb + (size_t)row * D_ + c4);
        *(float4*)&sK[row * QK_PAD + c4] = *(const float4*)(Kb + (size_t)row * D_ + c4);
    }
    __syncthreads();

    float acc[2][8][4];
#pragma unroll
    for (int mt = 0; mt < 2; mt++)
#pragma unroll
        for (int nt = 0; nt < 8; nt++)
#pragma unroll
            for (int r = 0; r < 4; r++) acc[mt][nt][r] = 0.0f;

#pragma unroll
    for (int ks = 0; ks < 8; ks++) {
        const int kb = ks * 8 + tg;

        uint32_t ahi[2][4], alo[2][4];
#pragma unroll
        for (int mt = 0; mt < 2; mt++) {
            int r = wm * 32 + mt * 16 + g;
            split_tf32(sQ[r * QK_PAD + kb],           ahi[mt][0], alo[mt][0]);
            split_tf32(sQ[(r + 8) * QK_PAD + kb],     ahi[mt][1], alo[mt][1]);
            split_tf32(sQ[r * QK_PAD + kb + 4],       ahi[mt][2], alo[mt][2]);
            split_tf32(sQ[(r + 8) * QK_PAD + kb + 4], ahi[mt][3], alo[mt][3]);
        }

        uint32_t bhi[8][2], blo[8][2];
#pragma unroll
        for (int nt = 0; nt < 8; nt++) {
            int cc = wn * 64 + nt * 8 + g;
            split_tf32(sK[cc * QK_PAD + kb],     bhi[nt][0], blo[nt][0]);
            split_tf32(sK[cc * QK_PAD + kb + 4], bhi[nt][1], blo[nt][1]);
        }

#pragma unroll
        for (int mt = 0; mt < 2; mt++)
#pragma unroll
            for (int nt = 0; nt < 8; nt++) {
                mma_tf32(acc[mt][nt], ahi[mt], bhi[nt]);
                mma_tf32(acc[mt][nt], ahi[mt], blo[nt]);
                mma_tf32(acc[mt][nt], alo[mt], bhi[nt]);
            }
    }

    // Epilogue: mask -> exp (masked -> 1.0, == expf(1e-9) in fp32), write E,
    // quad-reduce row partials, atomicAdd per row.
#pragma unroll
    for (int mt = 0; mt < 2; mt++)
#pragma unroll
        for (int rr = 0; rr < 2; rr++) {
            int qq = q0 + wm * 32 + mt * 16 + g + 8 * rr;
            float s = 0.0f;
#pragma unroll
            for (int nt = 0; nt < 8; nt++) {
                int kc = k0 + wn * 64 + nt * 8 + 2 * tg;
                int2 m2 = *(const int2*)(mask + ((size_t)b * S_ + qq) * S_ + kc);
                float e0 = (m2.x == 0) ? 1.0f : __expf(acc[mt][nt][2 * rr + 0] * SCALE_);
                float e1 = (m2.y == 0) ? 1.0f : __expf(acc[mt][nt][2 * rr + 1] * SCALE_);
                *(float2*)(attn + ((size_t)bh * S_ + qq) * S_ + kc) = make_float2(e0, e1);
                s += e0 + e1;
            }
            // reduce across the quad (tg = lane&3); qq is tg-invariant
            s += __shfl_xor_sync(0xffffffffu, s, 1);
            s += __shfl_xor_sync(0xffffffffu, s, 2);
            if (tg == 0)
                atomicAdd(&g_rowsum[(size_t)bh * S_ + qq], s);
        }
}

// ---------------------------------------------------------------------------
// Kernel 2: fused normalize + P writeback + O = P @ V (3xTF32, pre-split
// hi/lo smem planes; mainloop identical to R13/R14).
// Each CTA owns q-rows [q0, q0+128) exclusively -> in-place normalize is safe.
// ---------------------------------------------------------------------------
__global__ __launch_bounds__(256)
void av_tf32_kernel(float* __restrict__ attn, const float* __restrict__ v,
                    float* __restrict__ out)
{
    extern __shared__ uint32_t dsm[];
    uint32_t* sPhi  = dsm;                        // [128][AV_PAD]
    uint32_t* sPlo  = sPhi  + 128 * AV_PAD;       // [128][AV_PAD]
    uint32_t* sVhi  = sPlo  + 128 * AV_PAD;       // [64][AV_PAD] (transposed V)
    uint32_t* sVlo  = sVhi  + 64 * AV_PAD;        // [64][AV_PAD]
    __shared__ float sInv[128];

    const int bh = blockIdx.y;
    const int q0 = blockIdx.x * 128;
    const int t    = threadIdx.x;
    const int lane = t & 31;
    const int wid  = t >> 5;
    const int wm   = wid >> 1;        // 0..3 -> q rows [wm*32, +32)
    const int wn   = wid & 1;         // 0..1 -> d cols [wn*32, +32)
    const int g    = lane >> 2;
    const int tg   = lane & 3;

    float* Pb = attn + ((size_t)bh * S_ + q0) * S_;
    const float* Vb = v + (size_t)bh * S_ * D_;

    if (t < 128)
        sInv[t] = 1.0f / g_rowsum[(size_t)bh * S_ + q0 + t];
    __syncthreads();

    // V transpose-load mapping: lane = k-row (conflict-free STS), warp-constant d.
    const int vrow = t & 31;          // k-row within chunk
    const int vc4  = (t >> 5) * 4;    // d-offset 0..28 (with i*32: 0..60)

    float acc[2][4][4];
#pragma unroll
    for (int mt = 0; mt < 2; mt++)
#pragma unroll
        for (int nt = 0; nt < 4; nt++)
#pragma unroll
            for (int r = 0; r < 4; r++) acc[mt][nt][r] = 0.0f;

    for (int c0 = 0; c0 < S_; c0 += 32) {
        // E chunk 128x32: normalize, write P back in place, split into planes.
#pragma unroll
        for (int i = 0; i < 4; i++) {
            int vid = t + i * 256;
            int row = vid >> 3;           // 0..127
            int c4  = (vid & 7) * 4;      // 0..28
            float4 a = *(const float4*)(Pb + (size_t)row * S_ + c0 + c4);
            float inv = sInv[row];
            a.x *= inv; a.y *= inv; a.z *= inv; a.w *= inv;
            *(float4*)(Pb + (size_t)row * S_ + c0 + c4) = a;
            uint32_t hi, lo;
            split_tf32(a.x, hi, lo); sPhi[row * AV_PAD + c4 + 0] = hi; sPlo[row * AV_PAD + c4 + 0] = lo;
            split_tf32(a.y, hi, lo); sPhi[row * AV_PAD + c4 + 1] = hi; sPlo[row * AV_PAD + c4 + 1] = lo;
            split_tf32(a.z, hi, lo); sPhi[row * AV_PAD + c4 + 2] = hi; sPlo[row * AV_PAD + c4 + 2] = lo;
            split_tf32(a.w, hi, lo); sPhi[row * AV_PAD + c4 + 3] = hi; sPlo[row * AV_PAD + c4 + 3] = lo;
        }
        // V chunk 32x64 -> transposed [d][k]; split at store.
#pragma unroll
        for (int i = 0; i < 2; i++) {
            int dd = vc4 + i * 32;
            float4 bq = *(const float4*)(Vb + (size_t)(c0 + vrow) * D_ + dd);
            uint32_t hi, lo;
            split_tf32(bq.x, hi, lo); sVhi[(dd + 0) * AV_PAD + vrow] = hi; sVlo[(dd + 0) * AV_PAD + vrow] = lo;
            split_tf32(bq.y, hi, lo); sVhi[(dd + 1) * AV_PAD + vrow] = hi; sVlo[(dd + 1) * AV_PAD + vrow] = lo;
            split_tf32(bq.z, hi, lo); sVhi[(dd + 2) * AV_PAD + vrow] = hi; sVlo[(dd + 2) * AV_PAD + vrow] = lo;
            split_tf32(bq.w, hi, lo); sVhi[(dd + 3) * AV_PAD + vrow] = hi; sVlo[(dd + 3) * AV_PAD + vrow] = lo;
        }
        __syncthreads();

#pragma unroll
        for (int ks = 0; ks < 4; ks++) {
            const int kb = ks * 8 + tg;

            uint32_t ahi[2][4], alo[2][4];
#pragma unroll
            for (int mt = 0; mt < 2; mt++) {
                int r = wm * 32 + mt * 16 + g;
                ahi[mt][0] = sPhi[r * AV_PAD + kb];           alo[mt][0] = sPlo[r * AV_PAD + kb];
                ahi[mt][1] = sPhi[(r + 8) * AV_PAD + kb];     alo[mt][1] = sPlo[(r + 8) * AV_PAD + kb];
                ahi[mt][2] = sPhi[r * AV_PAD + kb + 4];       alo[mt][2] = sPlo[r * AV_PAD + kb + 4];
                ahi[mt][3] = sPhi[(r + 8) * AV_PAD + kb + 4]; alo[mt][3] = sPlo[(r + 8) * AV_PAD + kb + 4];
            }

            uint32_t bhi[4][2], blo[4][2];
#pragma unroll
            for (int nt = 0; nt < 4; nt++) {
                int cc = wn * 32 + nt * 8 + g;
                bhi[nt][0] = sVhi[cc * AV_PAD + kb];     blo[nt][0] = sVlo[cc * AV_PAD + kb];
                bhi[nt][1] = sVhi[cc * AV_PAD + kb + 4]; blo[nt][1] = sVlo[cc * AV_PAD + kb + 4];
            }

#pragma unroll
            for (int mt = 0; mt < 2; mt++)
#pragma unroll
                for (int nt = 0; nt < 4; nt++) {
                    mma_tf32(acc[mt][nt], ahi[mt], bhi[nt]);
                    mma_tf32(acc[mt][nt], ahi[mt], blo[nt]);
                    mma_tf32(acc[mt][nt], alo[mt], bhi[nt]);
                }
        }
        __syncthreads();
    }

    // Epilogue: O (already normalized; same C fragment layout as qk).
#pragma unroll
    for (int mt = 0; mt < 2; mt++)
#pragma unroll
        for (int nt = 0; nt < 4; nt++)
#pragma unroll
            for (int rr = 0; rr < 2; rr++) {
                int qq = q0 + wm * 32 + mt * 16 + g + 8 * rr;
                int dc = wn * 32 + nt * 8 + 2 * tg;
                float2 r;
                r.x = acc[mt][nt][2 * rr + 0];
                r.y = acc[mt][nt][2 * rr + 1];
                *(float2*)(out + ((size_t)bh * S_ + qq) * D_ + dc) = r;
            }
}

// ---------------------------------------------------------------------------
// Launch: out buffer = [output (B,H,S,D) | attention (B,H,S,S)]
// ---------------------------------------------------------------------------
extern "C" void kernel_launch(void* const* d_in, const int* in_sizes, int n_in,
                              void* d_out, int out_size)
{
    const float* q    = (const float*)d_in[0];
    const float* k    = (const float*)d_in[1];
    const float* v    = (const float*)d_in[2];
    const int*   mask = (const int*)d_in[3];

    float* out  = (float*)d_out;
    float* attn = out + (size_t)BH_ * S_ * D_;

    cudaFuncSetAttribute(qk_tf32_kernel,
                         cudaFuncAttributeMaxDynamicSharedMemorySize,
                         QK_SMEM_BYTES);
    cudaFuncSetAttribute(av_tf32_kernel,
                         cudaFuncAttributeMaxDynamicSharedMemorySize,
                         AV_SMEM_BYTES);

    zero_rowsum_kernel<<<(BH_ * S_) / 256, 256>>>();

    dim3 g1(S_ / 128, S_ / 128, BH_);
    qk_tf32_kernel<<<g1, 256, QK_SMEM_BYTES>>>(q, k, mask, attn);

    dim3 g3(S_ / 128, BH_);
    av_tf32_kernel<<<g3, 256, AV_SMEM_BYTES>>>(attn, v, out);
}